// round 6
// baseline (speedup 1.0000x reference)
#include <cuda_runtime.h>

#define BB 1024
#define TT 512
#define H1C 80
#define G1 320
#define H2C 100
#define G2 400

// Scratch (static device arrays: allocation-free per harness rules)
__device__ float g_h1[(size_t)TT * BB * H1C];      // relu(h1): 168 MB, layout [t][b][u]
__device__ float g_xg2[(size_t)TT * BB * G2];      // layer-2 gate pre-acts: 839 MB, [t][b][g]
__device__ float g_h2last[BB * H2C];               // relu(h2) at t=T-1
__device__ int   g_dummy_sink[32];

__device__ __forceinline__ float2 ffma2(float2 d, float2 a, float2 b) {
    unsigned long long dd = *reinterpret_cast<unsigned long long*>(&d);
    unsigned long long aa = *reinterpret_cast<unsigned long long*>(&a);
    unsigned long long bb = *reinterpret_cast<unsigned long long*>(&b);
    asm("fma.rn.f32x2 %0, %1, %2, %0;" : "+l"(dd) : "l"(aa), "l"(bb));
    return *reinterpret_cast<float2*>(&dd);
}

__device__ __forceinline__ float sigm(float x) { return 1.0f / (1.0f + __expf(-x)); }
__device__ __forceinline__ float tanh_(float x) { return 2.0f / (1.0f + __expf(-2.0f * x)) - 1.0f; }

// ---------------------------------------------------------------------------
// Kernel 1: layer-1 LSTM. 128 CTAs x 8 batches, persistent over T. 512 threads.
// Thread grid: 2 batch-halves (4 b each) x 8 k-groups (10 k) x 32 j-groups (10 j).
// 16 warps/CTA for latency hiding. Partials gs[kg][b][320] summed in activation.
// h stored duplicated as float2 (h,h); matvec reads 1 broadcast LDS.64/(k,b).
// ---------------------------------------------------------------------------
__global__ void __launch_bounds__(512, 1)
lstm1_kernel(const float* __restrict__ x, const float* __restrict__ W_ih1,
             const float* __restrict__ W_hh1, const float* __restrict__ b_ih1,
             const float* __restrict__ b_hh1) {
    extern __shared__ float sm[];
    float*  Wt   = sm;                          // 25600
    float*  wx   = Wt + 25600;                  // 320
    float*  bs   = wx + 320;                    // 320
    float2* hd   = (float2*)(bs + 320);         // 640 float2 [u*8+b]
    float*  gs   = (float*)(hd + 640);          // 20480  [kg][b][320]
    float*  xall = gs + 20480;                  // 4096   [b][t]

    const int tid = threadIdx.x;
    const int b0  = blockIdx.x * 8;

    for (int i = tid; i < G1 * H1C; i += 512) {
        int j = i / H1C, k = i - j * H1C;
        Wt[k * G1 + j] = W_hh1[i];
    }
    for (int i = tid; i < G1; i += 512) { wx[i] = W_ih1[i]; bs[i] = b_ih1[i] + b_hh1[i]; }
    for (int i = tid; i < 640; i += 512) hd[i] = make_float2(0.f, 0.f);
    for (int i = tid; i < 8 * TT; i += 512) {
        int b = i >> 9, t = i & 511;
        xall[i] = x[(size_t)(b0 + b) * TT + t];
    }
    __syncthreads();

    const int bh  = tid >> 8;         // batch half: 0 -> b 0..3, 1 -> b 4..7
    const int rem = tid & 255;
    const int kg  = rem >> 5;         // 8 k-groups of 10
    const int jg  = rem & 31;         // 32 j-groups of 10
    const int j0  = jg * 10;
    const int k0  = kg * 10;
    const int bb0 = bh * 4;

    // activation items: 640 (b,u) pairs over 512 threads -> 1 or 2 (tid<128 -> 2)
    const int nit = (tid < 128) ? 2 : 1;
    int itb[2], itu[2];
    float cst[2] = {0.f, 0.f};
#pragma unroll
    for (int r = 0; r < 2; ++r) {
        int it = tid + 512 * r;
        itb[r] = it / 80;
        itu[r] = it - itb[r] * 80;
    }

    for (int t = 0; t < TT; ++t) {
        // ---- matvec partials: k in [k0,k0+10), j in [j0,j0+10), 4 batches ----
        float2 a[5][4];
#pragma unroll
        for (int jp = 0; jp < 5; ++jp)
#pragma unroll
            for (int b = 0; b < 4; ++b) a[jp][b] = make_float2(0.f, 0.f);

        const float*  wp = Wt + k0 * G1 + j0;
        const float2* hp = hd + k0 * 8 + bb0;
#pragma unroll 5
        for (int k = 0; k < 10; ++k) {
            float2 w0 = *(const float2*)(wp + 0);
            float2 w1 = *(const float2*)(wp + 2);
            float2 w2 = *(const float2*)(wp + 4);
            float2 w3 = *(const float2*)(wp + 6);
            float2 w4 = *(const float2*)(wp + 8);
            wp += G1;
#pragma unroll
            for (int b = 0; b < 4; ++b) {
                float2 hb = hp[b];     // broadcast (h,h) within warp
                a[0][b] = ffma2(a[0][b], w0, hb);
                a[1][b] = ffma2(a[1][b], w1, hb);
                a[2][b] = ffma2(a[2][b], w2, hb);
                a[3][b] = ffma2(a[3][b], w3, hb);
                a[4][b] = ffma2(a[4][b], w4, hb);
            }
            hp += 8;
        }
        {
            float* gp0 = gs + kg * 2560 + bb0 * G1 + j0;
#pragma unroll
            for (int b = 0; b < 4; ++b)
#pragma unroll
                for (int jp = 0; jp < 5; ++jp)
                    *(float2*)(gp0 + b * G1 + jp * 2) = a[jp][b];
        }
        __syncthreads();

        // ---- activation: sum 8 partials + x*wx + bias ----
#pragma unroll
        for (int r = 0; r < 2; ++r) {
            if (r < nit) {
                const int b = itb[r], u = itu[r];
                const float xv = xall[b * TT + t];
                const float* gb = gs + b * G1;
                float s0 = xv * wx[u]       + bs[u];
                float s1 = xv * wx[80 + u]  + bs[80 + u];
                float s2 = xv * wx[160 + u] + bs[160 + u];
                float s3 = xv * wx[240 + u] + bs[240 + u];
#pragma unroll
                for (int q = 0; q < 8; ++q) {
                    const float* gq = gb + q * 2560;
                    s0 += gq[u];
                    s1 += gq[80 + u];
                    s2 += gq[160 + u];
                    s3 += gq[240 + u];
                }
                float ig = sigm(s0), fg = sigm(s1), gg = tanh_(s2), og = sigm(s3);
                float c = fg * cst[r] + ig * gg;
                cst[r] = c;
                float h = og * tanh_(c);
                hd[u * 8 + b] = make_float2(h, h);
                g_h1[(size_t)t * (BB * H1C) + (size_t)(b0 + b) * H1C + u] = fmaxf(h, 0.0f);
            }
        }
        __syncthreads();
    }
}

// ---------------------------------------------------------------------------
// Kernel 2: xg2 = relu(h1) @ W_ih2^T + bias.  Persistent, 148 blocks, 512 thr.
// 64-row tiles; 400 active threads = 8 rg x 50 cg, 8x8 thread tile.
// ---------------------------------------------------------------------------
__global__ void __launch_bounds__(512, 1)
xg2_gemm_kernel(const float* __restrict__ W_ih2, const float* __restrict__ b_ih2,
                const float* __restrict__ b_hh2) {
    extern __shared__ float sm[];
    float* Wt   = sm;            // 80*400 = 32000 (transposed W_ih2)
    float* bias = Wt + 32000;    // 400
    float* As   = bias + 400;    // 64*80 = 5120

    const int tid = threadIdx.x;
    for (int i = tid; i < G2 * H1C; i += 512) {
        int jj = i / H1C, k = i - jj * H1C;
        Wt[k * G2 + jj] = W_ih2[i];
    }
    for (int i = tid; i < G2; i += 512) bias[i] = b_ih2[i] + b_hh2[i];

    const int  rg  = tid / 50;
    const int  cg  = tid - rg * 50;
    const bool act = tid < 400;
    const int  NT  = (TT * BB) / 64;   // 8192 tiles

    for (int tile = blockIdx.x; tile < NT; tile += gridDim.x) {
        size_t r0 = (size_t)tile * 64;
        __syncthreads();
        for (int i = tid; i < 64 * H1C; i += 512) As[i] = g_h1[r0 * H1C + i];
        __syncthreads();
        if (act) {
            float2 acc[8][4];
#pragma unroll
            for (int i = 0; i < 8; ++i)
#pragma unroll
                for (int p = 0; p < 4; ++p) acc[i][p] = make_float2(0.f, 0.f);
            const float* ap = As + rg * 8 * H1C;
            const float* wp = Wt + cg * 8;
#pragma unroll 2
            for (int k = 0; k < H1C; ++k) {
                float2 w0 = *(const float2*)(wp + k * G2);
                float2 w1 = *(const float2*)(wp + k * G2 + 2);
                float2 w2 = *(const float2*)(wp + k * G2 + 4);
                float2 w3 = *(const float2*)(wp + k * G2 + 6);
#pragma unroll
                for (int i = 0; i < 8; ++i) {
                    float aval = ap[i * H1C + k];
                    float2 ad = make_float2(aval, aval);
                    acc[i][0] = ffma2(acc[i][0], w0, ad);
                    acc[i][1] = ffma2(acc[i][1], w1, ad);
                    acc[i][2] = ffma2(acc[i][2], w2, ad);
                    acc[i][3] = ffma2(acc[i][3], w3, ad);
                }
            }
            const int c = cg * 8;
#pragma unroll
            for (int i = 0; i < 8; ++i) {
                size_t row = r0 + (size_t)rg * 8 + i;
                float* op = g_xg2 + row * G2 + c;
#pragma unroll
                for (int p = 0; p < 4; ++p) {
                    float2 v = acc[i][p];
                    v.x += bias[c + 2 * p];
                    v.y += bias[c + 2 * p + 1];
                    *(float2*)(op + 2 * p) = v;
                }
            }
        }
    }
}

// ---------------------------------------------------------------------------
// Dummy kernel: shifts which launch ncu's fixed -s window captures (target:
// make lstm2 the 4th launch of each kernel_launch call).
// ---------------------------------------------------------------------------
__global__ void dummy_kernel() {
    if (threadIdx.x == 0) g_dummy_sink[blockIdx.x] = 1;
}

// ---------------------------------------------------------------------------
// Kernel 3: layer-2 LSTM. 128 CTAs x 8 batches, persistent over T. 512 threads.
// Thread grid: 2 batch-halves x (5 kg of 20 k x 50 jg of 8 j) = 500 active.
// xg prefetched via LDG at step top (hidden by k-loop).
// ---------------------------------------------------------------------------
__global__ void __launch_bounds__(512, 1)
lstm2_kernel(const float* __restrict__ W_hh2) {
    extern __shared__ float sm[];
    float*  Wt = sm;                      // 40000
    float2* hd = (float2*)(Wt + 40000);   // 800 float2 [u*8+b]
    float*  gs = (float*)(hd + 800);      // 16000  [kg][b][400]

    const int tid = threadIdx.x;
    const int b0  = blockIdx.x * 8;

    for (int i = tid; i < G2 * H2C; i += 512) {
        int jj = i / H2C, k = i - jj * H2C;
        Wt[k * G2 + jj] = W_hh2[i];
    }
    for (int i = tid; i < 800; i += 512) hd[i] = make_float2(0.f, 0.f);
    __syncthreads();

    const int  bh  = tid >> 8;            // batch half
    const int  rem = tid & 255;
    const bool act = rem < 250;
    const int  kg  = rem / 50;            // 5 k-groups of 20
    const int  jg  = rem - kg * 50;       // 50 j-groups of 8
    const int  j0  = jg * 8;
    const int  k0  = kg * 20;
    const int  bb0 = bh * 4;

    // activation items: 800 over 512 threads -> 1 or 2 (tid<288 -> 2)
    const int nit = (tid < 288) ? 2 : 1;
    int itb[2], itu[2];
    float cst[2] = {0.f, 0.f};
#pragma unroll
    for (int r = 0; r < 2; ++r) {
        int it = tid + 512 * r;
        itb[r] = it / 100;
        itu[r] = it - itb[r] * 100;
    }

    for (int t = 0; t < TT; ++t) {
        // ---- prefetch xg (hidden by k-loop) ----
        float xv[2][4];
#pragma unroll
        for (int r = 0; r < 2; ++r) {
            if (r < nit) {
                const float* xp = g_xg2 + (size_t)t * (BB * G2)
                                        + (size_t)(b0 + itb[r]) * G2 + itu[r];
                xv[r][0] = xp[0];
                xv[r][1] = xp[100];
                xv[r][2] = xp[200];
                xv[r][3] = xp[300];
            }
        }

        // ---- matvec partials: k in [k0,k0+20), j in [j0,j0+8), 4 batches ----
        if (act) {
            float2 a[4][4];
#pragma unroll
            for (int jp = 0; jp < 4; ++jp)
#pragma unroll
                for (int b = 0; b < 4; ++b) a[jp][b] = make_float2(0.f, 0.f);

            const float*  wp = Wt + k0 * G2 + j0;
            const float2* hp = hd + k0 * 8 + bb0;
#pragma unroll 5
            for (int k = 0; k < 20; ++k) {
                float4 wA = *(const float4*)(wp);
                float4 wB = *(const float4*)(wp + 4);
                wp += G2;
                float2 w0 = make_float2(wA.x, wA.y);
                float2 w1 = make_float2(wA.z, wA.w);
                float2 w2 = make_float2(wB.x, wB.y);
                float2 w3 = make_float2(wB.z, wB.w);
#pragma unroll
                for (int b = 0; b < 4; ++b) {
                    float2 hb = hp[b];
                    a[0][b] = ffma2(a[0][b], w0, hb);
                    a[1][b] = ffma2(a[1][b], w1, hb);
                    a[2][b] = ffma2(a[2][b], w2, hb);
                    a[3][b] = ffma2(a[3][b], w3, hb);
                }
                hp += 8;
            }
            float* gp0 = gs + kg * 3200 + bb0 * G2 + j0;
#pragma unroll
            for (int b = 0; b < 4; ++b)
#pragma unroll
                for (int jp = 0; jp < 4; ++jp)
                    *(float2*)(gp0 + b * G2 + jp * 2) = a[jp][b];
        }
        __syncthreads();

        // ---- activation: sum 5 partials + xg ----
#pragma unroll
        for (int r = 0; r < 2; ++r) {
            if (r < nit) {
                const int b = itb[r], u = itu[r];
                const float* gb = gs + b * G2;
                float s0 = xv[r][0], s1 = xv[r][1], s2 = xv[r][2], s3 = xv[r][3];
#pragma unroll
                for (int q = 0; q < 5; ++q) {
                    const float* gq = gb + q * 3200;
                    s0 += gq[u];
                    s1 += gq[100 + u];
                    s2 += gq[200 + u];
                    s3 += gq[300 + u];
                }
                float ig = sigm(s0), fg = sigm(s1), gg = tanh_(s2), og = sigm(s3);
                float c = fg * cst[r] + ig * gg;
                cst[r] = c;
                float h = og * tanh_(c);
                hd[u * 8 + b] = make_float2(h, h);
                if (t == TT - 1) g_h2last[(b0 + b) * H2C + u] = fmaxf(h, 0.0f);
            }
        }
        __syncthreads();
    }
}

// ---------------------------------------------------------------------------
// Kernel 4: final MLP head.
// ---------------------------------------------------------------------------
__global__ void fc_kernel(const float* __restrict__ W_l1, const float* __restrict__ b_l1,
                          const float* __restrict__ W_l2, const float* __restrict__ b_l2,
                          float* __restrict__ out) {
    __shared__ float wl1[10 * 100];
    __shared__ float bl1[10], wl2[10], bl2s;
    const int tid = threadIdx.x;
    for (int i = tid; i < 1000; i += 256) wl1[i] = W_l1[i];
    if (tid < 10) { bl1[tid] = b_l1[tid]; wl2[tid] = W_l2[tid]; }
    if (tid == 0) bl2s = b_l2[0];
    __syncthreads();

    const int b = blockIdx.x * 256 + tid;
    float acc[10];
#pragma unroll
    for (int jj = 0; jj < 10; ++jj) acc[jj] = bl1[jj];
    const float* hp = g_h2last + b * H2C;
    for (int k = 0; k < H2C; ++k) {
        float hk = hp[k];
#pragma unroll
        for (int jj = 0; jj < 10; ++jj) acc[jj] = fmaf(wl1[jj * 100 + k], hk, acc[jj]);
    }
    float o = bl2s;
#pragma unroll
    for (int jj = 0; jj < 10; ++jj) o += wl2[jj] * fmaxf(acc[jj], 0.0f);
    out[b] = o;
}

// ---------------------------------------------------------------------------
extern "C" void kernel_launch(void* const* d_in, const int* in_sizes, int n_in,
                              void* d_out, int out_size) {
    const float* x     = (const float*)d_in[0];
    const float* W_ih1 = (const float*)d_in[1];
    const float* W_hh1 = (const float*)d_in[2];
    const float* b_ih1 = (const float*)d_in[3];
    const float* b_hh1 = (const float*)d_in[4];
    const float* W_ih2 = (const float*)d_in[5];
    const float* W_hh2 = (const float*)d_in[6];
    const float* b_ih2 = (const float*)d_in[7];
    const float* b_hh2 = (const float*)d_in[8];
    const float* W_l1  = (const float*)d_in[9];
    const float* b_l1  = (const float*)d_in[10];
    const float* W_l2  = (const float*)d_in[11];
    const float* b_l2  = (const float*)d_in[12];

    const size_t smA = (size_t)(25600 + 320 + 320 + 1280 + 20480 + 4096) * 4; // 208384 B
    const size_t smG = (size_t)(32000 + 400 + 5120) * 4;                      // 150080 B
    const size_t smB = (size_t)(40000 + 1600 + 16000) * 4;                    // 230400 B

    cudaFuncSetAttribute(lstm1_kernel,    cudaFuncAttributeMaxDynamicSharedMemorySize, (int)smA);
    cudaFuncSetAttribute(xg2_gemm_kernel, cudaFuncAttributeMaxDynamicSharedMemorySize, (int)smG);
    cudaFuncSetAttribute(lstm2_kernel,    cudaFuncAttributeMaxDynamicSharedMemorySize, (int)smB);

    lstm1_kernel<<<128, 512, smA>>>(x, W_ih1, W_hh1, b_ih1, b_hh1);
    xg2_gemm_kernel<<<148, 512, smG>>>(W_ih2, b_ih2, b_hh2);
    dummy_kernel<<<1, 32>>>();                                  // capture-window shim
    lstm2_kernel<<<128, 512, smB>>>(W_hh2);
    fc_kernel<<<4, 256>>>(W_l1, b_l1, W_l2, b_l2, (float*)d_out);
}

// round 9
// speedup vs baseline: 1.2716x; 1.2716x over previous
#include <cuda_runtime.h>

#define BB 1024
#define TT 512
#define H1C 80
#define G1 320
#define H2C 100
#define G2 400

// Scratch (static device arrays: allocation-free per harness rules)
__device__ float g_h1[(size_t)TT * BB * H1C];      // relu(h1): 168 MB, layout [t][b][u]
__device__ float g_xg2[(size_t)TT * BB * G2];      // layer-2 gate pre-acts: 839 MB, [t][b][g]
__device__ float g_h2last[BB * H2C];               // relu(h2) at t=T-1
__device__ int   g_dummy_sink[32];

__device__ __forceinline__ float2 ffma2(float2 d, float2 a, float2 b) {
    unsigned long long dd = *reinterpret_cast<unsigned long long*>(&d);
    unsigned long long aa = *reinterpret_cast<unsigned long long*>(&a);
    unsigned long long bb = *reinterpret_cast<unsigned long long*>(&b);
    asm("fma.rn.f32x2 %0, %1, %2, %0;" : "+l"(dd) : "l"(aa), "l"(bb));
    return *reinterpret_cast<float2*>(&dd);
}

__device__ __forceinline__ float sigm(float x) { return 1.0f / (1.0f + __expf(-x)); }
__device__ __forceinline__ float tanh_(float x) { return 2.0f / (1.0f + __expf(-2.0f * x)) - 1.0f; }

// ---------------------------------------------------------------------------
// Kernel 1: layer-1 LSTM. 128 CTAs x 8 batches, 512 threads, persistent over T.
// Min-wavefront matvec: 400 active threads = 5 kg (16 k) x 80 jg (4 contig j).
// Per (thread,k): 1 coalesced LDS.128 (W, read once per step: 800 wf = minimal)
// + 2 broadcast LDS.128 (h[k][0..7], natural b-pairs) + 4 (w,w) packs
// + 16 FFMA2 over b-pairs. Partials gs[kg][bp][320][2], coalesced STS.128.
// ---------------------------------------------------------------------------
__global__ void __launch_bounds__(512, 1)
lstm1_kernel(const float* __restrict__ x, const float* __restrict__ W_ih1,
             const float* __restrict__ W_hh1, const float* __restrict__ b_ih1,
             const float* __restrict__ b_hh1) {
    extern __shared__ float sm[];
    float* Wt   = sm;                   // 25600  [k][j] (transposed W_hh1)
    float* wx   = Wt + 25600;           // 320
    float* bs   = wx + 320;             // 320
    float* hs   = bs + 320;             // 640    [k][b] plain
    float* gs   = hs + 640;             // 12800  [kg][bp][320][2]
    float* xall = gs + 12800;           // 4096   [b][t]

    const int tid = threadIdx.x;
    const int b0  = blockIdx.x * 8;

    for (int i = tid; i < G1 * H1C; i += 512) {
        int j = i / H1C, k = i - j * H1C;
        Wt[k * G1 + j] = W_hh1[i];
    }
    for (int i = tid; i < G1; i += 512) { wx[i] = W_ih1[i]; bs[i] = b_ih1[i] + b_hh1[i]; }
    for (int i = tid; i < 640; i += 512) hs[i] = 0.0f;
    for (int i = tid; i < 8 * TT; i += 512) {
        int b = i >> 9, t = i & 511;
        xall[i] = x[(size_t)(b0 + b) * TT + t];
    }
    __syncthreads();

    const bool act = tid < 400;
    const int  kg  = tid / 80;          // 5 k-groups of 16
    const int  jg  = tid - kg * 80;     // 80 j-groups of 4 contiguous
    const int  j0  = jg * 4;
    const int  k0  = kg * 16;

    // activation items: 640 (b,u) over 512 threads -> 1 or 2 (tid<128 -> 2)
    const int nit = (tid < 128) ? 2 : 1;
    int itb[2], itu[2];
    float cst[2] = {0.f, 0.f};
#pragma unroll
    for (int r = 0; r < 2; ++r) {
        int it = tid + 512 * r;
        itb[r] = it / 80;
        itu[r] = it - itb[r] * 80;
    }

    for (int t = 0; t < TT; ++t) {
        if (act) {
            float2 a[4][4];             // [j][bpair]
#pragma unroll
            for (int j = 0; j < 4; ++j)
#pragma unroll
                for (int bp = 0; bp < 4; ++bp) a[j][bp] = make_float2(0.f, 0.f);

            const float* wp = Wt + k0 * G1 + j0;
            const float* hp = hs + k0 * 8;
#pragma unroll 4
            for (int k = 0; k < 16; ++k) {
                float4 wv = *(const float4*)wp;       // coalesced across lanes
                float4 hA = *(const float4*)hp;       // broadcast
                float4 hB = *(const float4*)(hp + 4); // broadcast
                wp += G1; hp += 8;
                float2 hq[4] = {{hA.x, hA.y}, {hA.z, hA.w}, {hB.x, hB.y}, {hB.z, hB.w}};
                float2 wd[4] = {{wv.x, wv.x}, {wv.y, wv.y}, {wv.z, wv.z}, {wv.w, wv.w}};
#pragma unroll
                for (int j = 0; j < 4; ++j)
#pragma unroll
                    for (int bp = 0; bp < 4; ++bp)
                        a[j][bp] = ffma2(a[j][bp], wd[j], hq[bp]);
            }
            float* gp = gs + kg * 2560 + j0 * 2;      // [kg][bp][j][par]
#pragma unroll
            for (int bp = 0; bp < 4; ++bp) {
                float4 v0 = make_float4(a[0][bp].x, a[0][bp].y, a[1][bp].x, a[1][bp].y);
                float4 v1 = make_float4(a[2][bp].x, a[2][bp].y, a[3][bp].x, a[3][bp].y);
                *(float4*)(gp + bp * 640)     = v0;   // coalesced STS.128
                *(float4*)(gp + bp * 640 + 4) = v1;
            }
        }
        __syncthreads();

        // ---- activation: sum 5 partials + x*wx + bias ----
#pragma unroll
        for (int r = 0; r < 2; ++r) {
            if (r < nit) {
                const int b = itb[r], u = itu[r];
                const float xv = xall[b * TT + t];
                const float* gb = gs + (b >> 1) * 640 + (b & 1);
                float s0 = xv * wx[u]       + bs[u];
                float s1 = xv * wx[80 + u]  + bs[80 + u];
                float s2 = xv * wx[160 + u] + bs[160 + u];
                float s3 = xv * wx[240 + u] + bs[240 + u];
#pragma unroll
                for (int q = 0; q < 5; ++q) {
                    const float* gq = gb + q * 2560;
                    s0 += gq[u * 2];
                    s1 += gq[(80 + u) * 2];
                    s2 += gq[(160 + u) * 2];
                    s3 += gq[(240 + u) * 2];
                }
                float ig = sigm(s0), fg = sigm(s1), gg = tanh_(s2), og = sigm(s3);
                float c = fg * cst[r] + ig * gg;
                cst[r] = c;
                float h = og * tanh_(c);
                hs[u * 8 + b] = h;
                g_h1[(size_t)t * (BB * H1C) + (size_t)(b0 + b) * H1C + u] = fmaxf(h, 0.0f);
            }
        }
        __syncthreads();
    }
}

// ---------------------------------------------------------------------------
// Kernel 2: xg2 = relu(h1) @ W_ih2^T + bias.  Persistent, 148 blocks, 512 thr.
// (fma-bound per wavefront audit; unchanged)
// ---------------------------------------------------------------------------
__global__ void __launch_bounds__(512, 1)
xg2_gemm_kernel(const float* __restrict__ W_ih2, const float* __restrict__ b_ih2,
                const float* __restrict__ b_hh2) {
    extern __shared__ float sm[];
    float* Wt   = sm;            // 80*400 = 32000 (transposed W_ih2)
    float* bias = Wt + 32000;    // 400
    float* As   = bias + 400;    // 64*80 = 5120

    const int tid = threadIdx.x;
    for (int i = tid; i < G2 * H1C; i += 512) {
        int jj = i / H1C, k = i - jj * H1C;
        Wt[k * G2 + jj] = W_ih2[i];
    }
    for (int i = tid; i < G2; i += 512) bias[i] = b_ih2[i] + b_hh2[i];

    const int  rg  = tid / 50;
    const int  cg  = tid - rg * 50;
    const bool act = tid < 400;
    const int  NT  = (TT * BB) / 64;   // 8192 tiles

    for (int tile = blockIdx.x; tile < NT; tile += gridDim.x) {
        size_t r0 = (size_t)tile * 64;
        __syncthreads();
        for (int i = tid; i < 64 * H1C; i += 512) As[i] = g_h1[r0 * H1C + i];
        __syncthreads();
        if (act) {
            float2 acc[8][4];
#pragma unroll
            for (int i = 0; i < 8; ++i)
#pragma unroll
                for (int p = 0; p < 4; ++p) acc[i][p] = make_float2(0.f, 0.f);
            const float* ap = As + rg * 8 * H1C;
            const float* wp = Wt + cg * 8;
#pragma unroll 2
            for (int k = 0; k < H1C; ++k) {
                float2 w0 = *(const float2*)(wp + k * G2);
                float2 w1 = *(const float2*)(wp + k * G2 + 2);
                float2 w2 = *(const float2*)(wp + k * G2 + 4);
                float2 w3 = *(const float2*)(wp + k * G2 + 6);
#pragma unroll
                for (int i = 0; i < 8; ++i) {
                    float aval = ap[i * H1C + k];
                    float2 ad = make_float2(aval, aval);
                    acc[i][0] = ffma2(acc[i][0], w0, ad);
                    acc[i][1] = ffma2(acc[i][1], w1, ad);
                    acc[i][2] = ffma2(acc[i][2], w2, ad);
                    acc[i][3] = ffma2(acc[i][3], w3, ad);
                }
            }
            const int c = cg * 8;
#pragma unroll
            for (int i = 0; i < 8; ++i) {
                size_t row = r0 + (size_t)rg * 8 + i;
                float* op = g_xg2 + row * G2 + c;
#pragma unroll
                for (int p = 0; p < 4; ++p) {
                    float2 v = acc[i][p];
                    v.x += bias[c + 2 * p];
                    v.y += bias[c + 2 * p + 1];
                    *(float2*)(op + 2 * p) = v;
                }
            }
        }
    }
}

// ---------------------------------------------------------------------------
// Dummy kernel: keeps lstm2 as the 4th launch for ncu's fixed -s window.
// ---------------------------------------------------------------------------
__global__ void dummy_kernel() {
    if (threadIdx.x == 0) g_dummy_sink[blockIdx.x] = 1;
}

// ---------------------------------------------------------------------------
// Kernel 3: layer-2 LSTM. 128 CTAs x 8 batches, 512 threads, persistent over T.
// Min-wavefront matvec: 500 active = 5 kg (20 k) x 100 jg (4 contig j).
// W read once per step (1250 wf = 160 KB minimal). xg prefetch via LDG.
// ---------------------------------------------------------------------------
__global__ void __launch_bounds__(512, 1)
lstm2_kernel(const float* __restrict__ W_hh2) {
    extern __shared__ float sm[];
    float* Wt = sm;              // 40000  [k][j]
    float* hs = Wt + 40000;      // 800    [k][b] plain
    float* gs = hs + 800;        // 16000  [kg][bp][400][2]

    const int tid = threadIdx.x;
    const int b0  = blockIdx.x * 8;

    for (int i = tid; i < G2 * H2C; i += 512) {
        int jj = i / H2C, k = i - jj * H2C;
        Wt[k * G2 + jj] = W_hh2[i];
    }
    for (int i = tid; i < 800; i += 512) hs[i] = 0.0f;
    __syncthreads();

    const bool act = tid < 500;
    const int  kg  = tid / 100;         // 5 k-groups of 20
    const int  jg  = tid - kg * 100;    // 100 j-groups of 4 contiguous
    const int  j0  = jg * 4;
    const int  k0  = kg * 20;

    // activation items: 800 over 512 threads -> 1 or 2 (tid<288 -> 2)
    const int nit = (tid < 288) ? 2 : 1;
    int itb[2], itu[2];
    float cst[2] = {0.f, 0.f};
#pragma unroll
    for (int r = 0; r < 2; ++r) {
        int it = tid + 512 * r;
        itb[r] = it / 100;
        itu[r] = it - itb[r] * 100;
    }

    for (int t = 0; t < TT; ++t) {
        // ---- prefetch xg (hidden by k-loop) ----
        float xv[2][4];
#pragma unroll
        for (int r = 0; r < 2; ++r) {
            if (r < nit) {
                const float* xp = g_xg2 + (size_t)t * (BB * G2)
                                        + (size_t)(b0 + itb[r]) * G2 + itu[r];
                xv[r][0] = xp[0];
                xv[r][1] = xp[100];
                xv[r][2] = xp[200];
                xv[r][3] = xp[300];
            }
        }

        if (act) {
            float2 a[4][4];             // [j][bpair]
#pragma unroll
            for (int j = 0; j < 4; ++j)
#pragma unroll
                for (int bp = 0; bp < 4; ++bp) a[j][bp] = make_float2(0.f, 0.f);

            const float* wp = Wt + k0 * G2 + j0;
            const float* hp = hs + k0 * 8;
#pragma unroll 4
            for (int k = 0; k < 20; ++k) {
                float4 wv = *(const float4*)wp;       // coalesced across lanes
                float4 hA = *(const float4*)hp;       // broadcast
                float4 hB = *(const float4*)(hp + 4); // broadcast
                wp += G2; hp += 8;
                float2 hq[4] = {{hA.x, hA.y}, {hA.z, hA.w}, {hB.x, hB.y}, {hB.z, hB.w}};
                float2 wd[4] = {{wv.x, wv.x}, {wv.y, wv.y}, {wv.z, wv.z}, {wv.w, wv.w}};
#pragma unroll
                for (int j = 0; j < 4; ++j)
#pragma unroll
                    for (int bp = 0; bp < 4; ++bp)
                        a[j][bp] = ffma2(a[j][bp], wd[j], hq[bp]);
            }
            float* gp = gs + kg * 3200 + j0 * 2;      // [kg][bp][j][par]
#pragma unroll
            for (int bp = 0; bp < 4; ++bp) {
                float4 v0 = make_float4(a[0][bp].x, a[0][bp].y, a[1][bp].x, a[1][bp].y);
                float4 v1 = make_float4(a[2][bp].x, a[2][bp].y, a[3][bp].x, a[3][bp].y);
                *(float4*)(gp + bp * 800)     = v0;   // coalesced STS.128
                *(float4*)(gp + bp * 800 + 4) = v1;
            }
        }
        __syncthreads();

        // ---- activation: sum 5 partials + xg ----
#pragma unroll
        for (int r = 0; r < 2; ++r) {
            if (r < nit) {
                const int b = itb[r], u = itu[r];
                const float* gb = gs + (b >> 1) * 800 + (b & 1);
                float s0 = xv[r][0], s1 = xv[r][1], s2 = xv[r][2], s3 = xv[r][3];
#pragma unroll
                for (int q = 0; q < 5; ++q) {
                    const float* gq = gb + q * 3200;
                    s0 += gq[u * 2];
                    s1 += gq[(100 + u) * 2];
                    s2 += gq[(200 + u) * 2];
                    s3 += gq[(300 + u) * 2];
                }
                float ig = sigm(s0), fg = sigm(s1), gg = tanh_(s2), og = sigm(s3);
                float c = fg * cst[r] + ig * gg;
                cst[r] = c;
                float h = og * tanh_(c);
                hs[u * 8 + b] = h;
                if (t == TT - 1) g_h2last[(b0 + b) * H2C + u] = fmaxf(h, 0.0f);
            }
        }
        __syncthreads();
    }
}

// ---------------------------------------------------------------------------
// Kernel 4: final MLP head.
// ---------------------------------------------------------------------------
__global__ void fc_kernel(const float* __restrict__ W_l1, const float* __restrict__ b_l1,
                          const float* __restrict__ W_l2, const float* __restrict__ b_l2,
                          float* __restrict__ out) {
    __shared__ float wl1[10 * 100];
    __shared__ float bl1[10], wl2[10], bl2s;
    const int tid = threadIdx.x;
    for (int i = tid; i < 1000; i += 256) wl1[i] = W_l1[i];
    if (tid < 10) { bl1[tid] = b_l1[tid]; wl2[tid] = W_l2[tid]; }
    if (tid == 0) bl2s = b_l2[0];
    __syncthreads();

    const int b = blockIdx.x * 256 + tid;
    float acc[10];
#pragma unroll
    for (int jj = 0; jj < 10; ++jj) acc[jj] = bl1[jj];
    const float* hp = g_h2last + b * H2C;
    for (int k = 0; k < H2C; ++k) {
        float hk = hp[k];
#pragma unroll
        for (int jj = 0; jj < 10; ++jj) acc[jj] = fmaf(wl1[jj * 100 + k], hk, acc[jj]);
    }
    float o = bl2s;
#pragma unroll
    for (int jj = 0; jj < 10; ++jj) o += wl2[jj] * fmaxf(acc[jj], 0.0f);
    out[b] = o;
}

// ---------------------------------------------------------------------------
extern "C" void kernel_launch(void* const* d_in, const int* in_sizes, int n_in,
                              void* d_out, int out_size) {
    const float* x     = (const float*)d_in[0];
    const float* W_ih1 = (const float*)d_in[1];
    const float* W_hh1 = (const float*)d_in[2];
    const float* b_ih1 = (const float*)d_in[3];
    const float* b_hh1 = (const float*)d_in[4];
    const float* W_ih2 = (const float*)d_in[5];
    const float* W_hh2 = (const float*)d_in[6];
    const float* b_ih2 = (const float*)d_in[7];
    const float* b_hh2 = (const float*)d_in[8];
    const float* W_l1  = (const float*)d_in[9];
    const float* b_l1  = (const float*)d_in[10];
    const float* W_l2  = (const float*)d_in[11];
    const float* b_l2  = (const float*)d_in[12];

    const size_t smA = (size_t)(25600 + 320 + 320 + 640 + 12800 + 4096) * 4;  // 175104 B
    const size_t smG = (size_t)(32000 + 400 + 5120) * 4;                      // 150080 B
    const size_t smB = (size_t)(40000 + 800 + 16000) * 4;                     // 227200 B

    cudaFuncSetAttribute(lstm1_kernel,    cudaFuncAttributeMaxDynamicSharedMemorySize, (int)smA);
    cudaFuncSetAttribute(xg2_gemm_kernel, cudaFuncAttributeMaxDynamicSharedMemorySize, (int)smG);
    cudaFuncSetAttribute(lstm2_kernel,    cudaFuncAttributeMaxDynamicSharedMemorySize, (int)smB);

    lstm1_kernel<<<128, 512, smA>>>(x, W_ih1, W_hh1, b_ih1, b_hh1);
    xg2_gemm_kernel<<<148, 512, smG>>>(W_ih2, b_ih2, b_hh2);
    dummy_kernel<<<1, 32>>>();                                  // capture-window shim
    lstm2_kernel<<<128, 512, smB>>>(W_hh2);
    fc_kernel<<<4, 256>>>(W_l1, b_l1, W_l2, b_l2, (float*)d_out);
}

// round 12
// speedup vs baseline: 1.3711x; 1.0782x over previous
#include <cuda_runtime.h>

#define BB 1024
#define TT 512
#define H1C 80
#define G1 320
#define H2C 100
#define G2 400

// Scratch (static device arrays: allocation-free per harness rules)
__device__ float g_h1[(size_t)TT * BB * H1C];      // relu(h1): 168 MB, layout [t][b][u]
__device__ float g_xg2[(size_t)TT * BB * G2];      // layer-2 gate pre-acts: 839 MB, [t][b][g]
__device__ float g_h2last[BB * H2C];               // relu(h2) at t=T-1
__device__ int   g_dummy_sink[32];

__device__ __forceinline__ float2 ffma2(float2 d, float2 a, float2 b) {
    unsigned long long dd = *reinterpret_cast<unsigned long long*>(&d);
    unsigned long long aa = *reinterpret_cast<unsigned long long*>(&a);
    unsigned long long bb = *reinterpret_cast<unsigned long long*>(&b);
    asm("fma.rn.f32x2 %0, %1, %2, %0;" : "+l"(dd) : "l"(aa), "l"(bb));
    return *reinterpret_cast<float2*>(&dd);
}

__device__ __forceinline__ float sigm(float x) { return 1.0f / (1.0f + __expf(-x)); }
__device__ __forceinline__ float tanh_(float x) { return 2.0f / (1.0f + __expf(-2.0f * x)) - 1.0f; }

// ---------------------------------------------------------------------------
// Kernel 1: layer-1 LSTM. 128 CTAs x 8 batches, 512 threads, persistent over T.
// W_hh1 REGISTER-RESIDENT: 400 active threads = 5 kg (16 k) x 80 jg (4 j),
// wreg[4][16] loaded once. Batches in 2 half-passes (4 b) to cap accumulators.
// Partials gs[kg][bp][par][320]: coalesced STS.128 stores, stride-1 gathers.
// ---------------------------------------------------------------------------
__global__ void __launch_bounds__(512, 1)
lstm1_kernel(const float* __restrict__ x, const float* __restrict__ W_ih1,
             const float* __restrict__ W_hh1, const float* __restrict__ b_ih1,
             const float* __restrict__ b_hh1) {
    extern __shared__ float sm[];
    float* wx   = sm;                   // 320
    float* bs   = wx + 320;             // 320
    float* hs   = bs + 320;             // 640    [k][b] plain
    float* gs   = hs + 640;             // 12800  [kg][bp][par][320]
    float* xall = gs + 12800;           // 4096   [b][t]

    const int tid = threadIdx.x;
    const int b0  = blockIdx.x * 8;

    for (int i = tid; i < G1; i += 512) { wx[i] = W_ih1[i]; bs[i] = b_ih1[i] + b_hh1[i]; }
    for (int i = tid; i < 640; i += 512) hs[i] = 0.0f;
    for (int i = tid; i < 8 * TT; i += 512) {
        int b = i >> 9, t = i & 511;
        xall[i] = x[(size_t)(b0 + b) * TT + t];
    }

    const bool act = tid < 400;
    const int  kg  = tid / 80;          // 5 k-groups of 16
    const int  jg  = tid - kg * 80;     // 80 j-groups of 4
    const int  j0  = jg * 4;
    const int  k0  = kg * 16;

    // W block -> registers (one-time LDG; g[j] = sum_k h[k]*W_hh1[j][k])
    float wreg[4][16];
    if (act) {
#pragma unroll
        for (int j = 0; j < 4; ++j)
#pragma unroll
            for (int kq = 0; kq < 4; ++kq)
                *(float4*)&wreg[j][kq * 4] =
                    *(const float4*)(W_hh1 + (size_t)(j0 + j) * H1C + k0 + kq * 4);
    }
    __syncthreads();

    // activation items: 640 (b,u) over 512 threads -> 1 or 2 (tid<128 -> 2)
    const int nit = (tid < 128) ? 2 : 1;
    int itb[2], itu[2];
    float cst[2] = {0.f, 0.f};
#pragma unroll
    for (int r = 0; r < 2; ++r) {
        int it = tid + 512 * r;
        itb[r] = it / 80;
        itu[r] = it - itb[r] * 80;
    }

    for (int t = 0; t < TT; ++t) {
        if (act) {
#pragma unroll
            for (int pass = 0; pass < 2; ++pass) {   // batches pass*4 .. pass*4+3
                float2 a[4][2];
#pragma unroll
                for (int j = 0; j < 4; ++j) { a[j][0] = make_float2(0.f, 0.f); a[j][1] = make_float2(0.f, 0.f); }
                const float* hp = hs + pass * 4 + k0 * 8;
#pragma unroll
                for (int k = 0; k < 16; ++k) {
                    float4 hv = *(const float4*)(hp + k * 8);  // broadcast, b-quad
                    float2 hq0 = make_float2(hv.x, hv.y);
                    float2 hq1 = make_float2(hv.z, hv.w);
#pragma unroll
                    for (int j = 0; j < 4; ++j) {
                        float2 wd = make_float2(wreg[j][k], wreg[j][k]);
                        a[j][0] = ffma2(a[j][0], wd, hq0);
                        a[j][1] = ffma2(a[j][1], wd, hq1);
                    }
                }
                // store: [kg][bp][par][320]
                float* gp = gs + kg * 2560 + pass * 2 * 640 + j0;
#pragma unroll
                for (int bq = 0; bq < 2; ++bq) {
                    *(float4*)(gp + bq * 640)       = make_float4(a[0][bq].x, a[1][bq].x, a[2][bq].x, a[3][bq].x);
                    *(float4*)(gp + bq * 640 + 320) = make_float4(a[0][bq].y, a[1][bq].y, a[2][bq].y, a[3][bq].y);
                }
            }
        }
        __syncthreads();

        // ---- activation: sum 5 partials + x*wx + bias (stride-1 gathers) ----
#pragma unroll
        for (int r = 0; r < 2; ++r) {
            if (r < nit) {
                const int b = itb[r], u = itu[r];
                const float xv = xall[b * TT + t];
                const float* gb = gs + ((b >> 1) * 2 + (b & 1)) * 320;
                float s0 = xv * wx[u]       + bs[u];
                float s1 = xv * wx[80 + u]  + bs[80 + u];
                float s2 = xv * wx[160 + u] + bs[160 + u];
                float s3 = xv * wx[240 + u] + bs[240 + u];
#pragma unroll
                for (int q = 0; q < 5; ++q) {
                    const float* gq = gb + q * 2560;
                    s0 += gq[u];
                    s1 += gq[80 + u];
                    s2 += gq[160 + u];
                    s3 += gq[240 + u];
                }
                float ig = sigm(s0), fg = sigm(s1), gg = tanh_(s2), og = sigm(s3);
                float c = fg * cst[r] + ig * gg;
                cst[r] = c;
                float h = og * tanh_(c);
                hs[u * 8 + b] = h;
                g_h1[(size_t)t * (BB * H1C) + (size_t)(b0 + b) * H1C + u] = fmaxf(h, 0.0f);
            }
        }
        __syncthreads();
    }
}

// ---------------------------------------------------------------------------
// Kernel 2: xg2 = relu(h1) @ W_ih2^T + bias.  Persistent, 148 blocks, 512 thr.
// (fma-bound per wavefront audit; unchanged)
// ---------------------------------------------------------------------------
__global__ void __launch_bounds__(512, 1)
xg2_gemm_kernel(const float* __restrict__ W_ih2, const float* __restrict__ b_ih2,
                const float* __restrict__ b_hh2) {
    extern __shared__ float sm[];
    float* Wt   = sm;            // 80*400 = 32000 (transposed W_ih2)
    float* bias = Wt + 32000;    // 400
    float* As   = bias + 400;    // 64*80 = 5120

    const int tid = threadIdx.x;
    for (int i = tid; i < G2 * H1C; i += 512) {
        int jj = i / H1C, k = i - jj * H1C;
        Wt[k * G2 + jj] = W_ih2[i];
    }
    for (int i = tid; i < G2; i += 512) bias[i] = b_ih2[i] + b_hh2[i];

    const int  rg  = tid / 50;
    const int  cg  = tid - rg * 50;
    const bool act = tid < 400;
    const int  NT  = (TT * BB) / 64;   // 8192 tiles

    for (int tile = blockIdx.x; tile < NT; tile += gridDim.x) {
        size_t r0 = (size_t)tile * 64;
        __syncthreads();
        for (int i = tid; i < 64 * H1C; i += 512) As[i] = g_h1[r0 * H1C + i];
        __syncthreads();
        if (act) {
            float2 acc[8][4];
#pragma unroll
            for (int i = 0; i < 8; ++i)
#pragma unroll
                for (int p = 0; p < 4; ++p) acc[i][p] = make_float2(0.f, 0.f);
            const float* ap = As + rg * 8 * H1C;
            const float* wp = Wt + cg * 8;
#pragma unroll 2
            for (int k = 0; k < H1C; ++k) {
                float2 w0 = *(const float2*)(wp + k * G2);
                float2 w1 = *(const float2*)(wp + k * G2 + 2);
                float2 w2 = *(const float2*)(wp + k * G2 + 4);
                float2 w3 = *(const float2*)(wp + k * G2 + 6);
#pragma unroll
                for (int i = 0; i < 8; ++i) {
                    float aval = ap[i * H1C + k];
                    float2 ad = make_float2(aval, aval);
                    acc[i][0] = ffma2(acc[i][0], w0, ad);
                    acc[i][1] = ffma2(acc[i][1], w1, ad);
                    acc[i][2] = ffma2(acc[i][2], w2, ad);
                    acc[i][3] = ffma2(acc[i][3], w3, ad);
                }
            }
            const int c = cg * 8;
#pragma unroll
            for (int i = 0; i < 8; ++i) {
                size_t row = r0 + (size_t)rg * 8 + i;
                float* op = g_xg2 + row * G2 + c;
#pragma unroll
                for (int p = 0; p < 4; ++p) {
                    float2 v = acc[i][p];
                    v.x += bias[c + 2 * p];
                    v.y += bias[c + 2 * p + 1];
                    *(float2*)(op + 2 * p) = v;
                }
            }
        }
    }
}

// ---------------------------------------------------------------------------
// Dummy kernel: keeps lstm2 as the 4th launch for ncu's fixed -s window.
// ---------------------------------------------------------------------------
__global__ void dummy_kernel() {
    if (threadIdx.x == 0) g_dummy_sink[blockIdx.x] = 1;
}

// ---------------------------------------------------------------------------
// Kernel 3: layer-2 LSTM. 128 CTAs x 8 batches, 512 threads, persistent over T.
// W_hh2 REGISTER-RESIDENT: 500 active = 5 kg (20 k) x 100 jg (4 j), wreg[4][20].
// Batches in 2 half-passes. gs[kg][bp][par][400]. xg prefetch via LDG.
// ---------------------------------------------------------------------------
__global__ void __launch_bounds__(512, 1)
lstm2_kernel(const float* __restrict__ W_hh2) {
    extern __shared__ float sm[];
    float* hs = sm;              // 800    [k][b] plain
    float* gs = hs + 800;        // 16000  [kg][bp][par][400]

    const int tid = threadIdx.x;
    const int b0  = blockIdx.x * 8;

    for (int i = tid; i < 800; i += 512) hs[i] = 0.0f;

    const bool act = tid < 500;
    const int  kg  = tid / 100;         // 5 k-groups of 20
    const int  jg  = tid - kg * 100;    // 100 j-groups of 4
    const int  j0  = jg * 4;
    const int  k0  = kg * 20;

    // W block -> registers (one-time LDG)
    float wreg[4][20];
    if (act) {
#pragma unroll
        for (int j = 0; j < 4; ++j)
#pragma unroll
            for (int kq = 0; kq < 5; ++kq)
                *(float4*)&wreg[j][kq * 4] =
                    *(const float4*)(W_hh2 + (size_t)(j0 + j) * H2C + k0 + kq * 4);
    }
    __syncthreads();

    // activation items: 800 over 512 threads -> 1 or 2 (tid<288 -> 2)
    const int nit = (tid < 288) ? 2 : 1;
    int itb[2], itu[2];
    float cst[2] = {0.f, 0.f};
#pragma unroll
    for (int r = 0; r < 2; ++r) {
        int it = tid + 512 * r;
        itb[r] = it / 100;
        itu[r] = it - itb[r] * 100;
    }

    for (int t = 0; t < TT; ++t) {
        // ---- prefetch xg (hidden by matvec) ----
        float xv[2][4];
#pragma unroll
        for (int r = 0; r < 2; ++r) {
            if (r < nit) {
                const float* xp = g_xg2 + (size_t)t * (BB * G2)
                                        + (size_t)(b0 + itb[r]) * G2 + itu[r];
                xv[r][0] = xp[0];
                xv[r][1] = xp[100];
                xv[r][2] = xp[200];
                xv[r][3] = xp[300];
            }
        }

        if (act) {
#pragma unroll
            for (int pass = 0; pass < 2; ++pass) {   // batches pass*4 .. pass*4+3
                float2 a[4][2];
#pragma unroll
                for (int j = 0; j < 4; ++j) { a[j][0] = make_float2(0.f, 0.f); a[j][1] = make_float2(0.f, 0.f); }
                const float* hp = hs + pass * 4 + k0 * 8;
#pragma unroll
                for (int k = 0; k < 20; ++k) {
                    float4 hv = *(const float4*)(hp + k * 8);  // broadcast, b-quad
                    float2 hq0 = make_float2(hv.x, hv.y);
                    float2 hq1 = make_float2(hv.z, hv.w);
#pragma unroll
                    for (int j = 0; j < 4; ++j) {
                        float2 wd = make_float2(wreg[j][k], wreg[j][k]);
                        a[j][0] = ffma2(a[j][0], wd, hq0);
                        a[j][1] = ffma2(a[j][1], wd, hq1);
                    }
                }
                // store: [kg][bp][par][400]
                float* gp = gs + kg * 3200 + pass * 2 * 800 + j0;
#pragma unroll
                for (int bq = 0; bq < 2; ++bq) {
                    *(float4*)(gp + bq * 800)       = make_float4(a[0][bq].x, a[1][bq].x, a[2][bq].x, a[3][bq].x);
                    *(float4*)(gp + bq * 800 + 400) = make_float4(a[0][bq].y, a[1][bq].y, a[2][bq].y, a[3][bq].y);
                }
            }
        }
        __syncthreads();

        // ---- activation: sum 5 partials + xg (stride-1 gathers) ----
#pragma unroll
        for (int r = 0; r < 2; ++r) {
            if (r < nit) {
                const int b = itb[r], u = itu[r];
                const float* gb = gs + ((b >> 1) * 2 + (b & 1)) * 400;
                float s0 = xv[r][0], s1 = xv[r][1], s2 = xv[r][2], s3 = xv[r][3];
#pragma unroll
                for (int q = 0; q < 5; ++q) {
                    const float* gq = gb + q * 3200;
                    s0 += gq[u];
                    s1 += gq[100 + u];
                    s2 += gq[200 + u];
                    s3 += gq[300 + u];
                }
                float ig = sigm(s0), fg = sigm(s1), gg = tanh_(s2), og = sigm(s3);
                float c = fg * cst[r] + ig * gg;
                cst[r] = c;
                float h = og * tanh_(c);
                hs[u * 8 + b] = h;
                if (t == TT - 1) g_h2last[(b0 + b) * H2C + u] = fmaxf(h, 0.0f);
            }
        }
        __syncthreads();
    }
}

// ---------------------------------------------------------------------------
// Kernel 4: final MLP head.
// ---------------------------------------------------------------------------
__global__ void fc_kernel(const float* __restrict__ W_l1, const float* __restrict__ b_l1,
                          const float* __restrict__ W_l2, const float* __restrict__ b_l2,
                          float* __restrict__ out) {
    __shared__ float wl1[10 * 100];
    __shared__ float bl1[10], wl2[10], bl2s;
    const int tid = threadIdx.x;
    for (int i = tid; i < 1000; i += 256) wl1[i] = W_l1[i];
    if (tid < 10) { bl1[tid] = b_l1[tid]; wl2[tid] = W_l2[tid]; }
    if (tid == 0) bl2s = b_l2[0];
    __syncthreads();

    const int b = blockIdx.x * 256 + tid;
    float acc[10];
#pragma unroll
    for (int jj = 0; jj < 10; ++jj) acc[jj] = bl1[jj];
    const float* hp = g_h2last + b * H2C;
    for (int k = 0; k < H2C; ++k) {
        float hk = hp[k];
#pragma unroll
        for (int jj = 0; jj < 10; ++jj) acc[jj] = fmaf(wl1[jj * 100 + k], hk, acc[jj]);
    }
    float o = bl2s;
#pragma unroll
    for (int jj = 0; jj < 10; ++jj) o += wl2[jj] * fmaxf(acc[jj], 0.0f);
    out[b] = o;
}

// ---------------------------------------------------------------------------
extern "C" void kernel_launch(void* const* d_in, const int* in_sizes, int n_in,
                              void* d_out, int out_size) {
    const float* x     = (const float*)d_in[0];
    const float* W_ih1 = (const float*)d_in[1];
    const float* W_hh1 = (const float*)d_in[2];
    const float* b_ih1 = (const float*)d_in[3];
    const float* b_hh1 = (const float*)d_in[4];
    const float* W_ih2 = (const float*)d_in[5];
    const float* W_hh2 = (const float*)d_in[6];
    const float* b_ih2 = (const float*)d_in[7];
    const float* b_hh2 = (const float*)d_in[8];
    const float* W_l1  = (const float*)d_in[9];
    const float* b_l1  = (const float*)d_in[10];
    const float* W_l2  = (const float*)d_in[11];
    const float* b_l2  = (const float*)d_in[12];

    const size_t smA = (size_t)(320 + 320 + 640 + 12800 + 4096) * 4;  // 72704 B
    const size_t smG = (size_t)(32000 + 400 + 5120) * 4;              // 150080 B
    const size_t smB = (size_t)(800 + 16000) * 4;                     // 67200 B

    cudaFuncSetAttribute(lstm1_kernel,    cudaFuncAttributeMaxDynamicSharedMemorySize, (int)smA);
    cudaFuncSetAttribute(xg2_gemm_kernel, cudaFuncAttributeMaxDynamicSharedMemorySize, (int)smG);
    cudaFuncSetAttribute(lstm2_kernel,    cudaFuncAttributeMaxDynamicSharedMemorySize, (int)smB);

    lstm1_kernel<<<128, 512, smA>>>(x, W_ih1, W_hh1, b_ih1, b_hh1);
    xg2_gemm_kernel<<<148, 512, smG>>>(W_ih2, b_ih2, b_hh2);
    dummy_kernel<<<1, 32>>>();                                  // capture-window shim
    lstm2_kernel<<<128, 512, smB>>>(W_hh2);
    fc_kernel<<<4, 256>>>(W_l1, b_l1, W_l2, b_l2, (float*)d_out);
}